// round 1
// baseline (speedup 1.0000x reference)
#include <cuda_runtime.h>
#include <math.h>

// Problem constants
#define HH 1024
#define WW 1024
#define NHH 63
#define NP 3969            // 63*63 patches
#define H1_PER 15000       // 24*25*25
#define H2_PER 26460       // 60*21*21
#define H3_PER 15000       // 24*25*25

// Intermediate buffers (static device globals; no allocation allowed)
__device__ float g_h1[(size_t)NP * H1_PER];
__device__ float g_h2[(size_t)NP * H2_PER];
__device__ float g_h3[(size_t)NP * H3_PER];
__device__ float g_p [(size_t)NP * 1024];

__device__ __forceinline__ float elu1(float v) {
    return v > 0.f ? v : expm1f(v);
}

// ---------------------------------------------------------------------------
// K1: conv1 (3D, kernel 2x8x8, VALID) + ELU
// out h1[n][c=24][25][25]; patch depth0=x1, depth1=x2
// ---------------------------------------------------------------------------
__global__ void conv1_kernel(const float* __restrict__ x1,
                             const float* __restrict__ x2,
                             const float* __restrict__ w,   // [24][1][2][8][8]
                             const float* __restrict__ b,   // [24]
                             float* __restrict__ h1) {
    __shared__ float sP[2][32][32];
    __shared__ float sW[3072];
    __shared__ float sB[24];
    const int n = blockIdx.x;
    const int iy = n / NHH, ix = n % NHH;
    const int bd = blockDim.x;

    for (int i = threadIdx.x; i < 2048; i += bd) {
        int d = i >> 10, rem = i & 1023;
        int wy = rem >> 5, wx = rem & 31;
        const float* xs = d ? x2 : x1;
        sP[d][wy][wx] = xs[(iy * 16 + wy) * WW + ix * 16 + wx];
    }
    for (int i = threadIdx.x; i < 3072; i += bd) sW[i] = w[i];
    if (threadIdx.x < 24) sB[threadIdx.x] = b[threadIdx.x];
    __syncthreads();

    // 600 output rows: r = c*25 + oy, each row has 25 outputs
    for (int r = threadIdx.x; r < 600; r += bd) {
        int c = r / 25, oy = r % 25;
        float acc[25];
        float bias = sB[c];
#pragma unroll
        for (int x = 0; x < 25; x++) acc[x] = bias;
#pragma unroll
        for (int d = 0; d < 2; d++) {
#pragma unroll
            for (int ky = 0; ky < 8; ky++) {
                float reg[32];
                const float* row = &sP[d][oy + ky][0];
#pragma unroll
                for (int i = 0; i < 32; i++) reg[i] = row[i];
                const float* wr = sW + c * 128 + d * 64 + ky * 8;
#pragma unroll
                for (int kx = 0; kx < 8; kx++) {
                    float wv = wr[kx];
#pragma unroll
                    for (int x = 0; x < 25; x++) acc[x] = fmaf(reg[x + kx], wv, acc[x]);
                }
            }
        }
        float* outp = h1 + (size_t)n * H1_PER + r * 25;
#pragma unroll
        for (int x = 0; x < 25; x++) outp[x] = elu1(acc[x]);
    }
}

// ---------------------------------------------------------------------------
// K2: conv2 (2D 5x5 VALID, 24->60) + ReLU
// in h1[n][24][25][25], out h2[n][60][21][21]
// smem: input 15000 + weights 36000 floats = 204000 B
// ---------------------------------------------------------------------------
__global__ void conv2_kernel(const float* __restrict__ h1,
                             const float* __restrict__ w,   // [60][24][5][5]
                             const float* __restrict__ b,   // [60]
                             float* __restrict__ h2) {
    extern __shared__ float sm[];
    float* sIn = sm;          // 15000
    float* sW  = sm + 15000;  // 36000
    const int n = blockIdx.x;
    const int bd = blockDim.x;
    const float* in = h1 + (size_t)n * H1_PER;
    for (int i = threadIdx.x; i < H1_PER; i += bd) sIn[i] = in[i];
    for (int i = threadIdx.x; i < 36000; i += bd) sW[i] = w[i];
    __syncthreads();

    // 1260 rows: r = co*21 + y, each 21 outputs
    for (int r = threadIdx.x; r < 1260; r += bd) {
        int co = r / 21, y = r % 21;
        float acc[21];
        float bias = b[co];
#pragma unroll
        for (int x = 0; x < 21; x++) acc[x] = bias;
        for (int ci = 0; ci < 24; ci++) {
            const float* inc = sIn + ci * 625;
            const float* wc = sW + co * 600 + ci * 25;
#pragma unroll
            for (int ky = 0; ky < 5; ky++) {
                float reg[25];
                const float* row = inc + (y + ky) * 25;
#pragma unroll
                for (int i = 0; i < 25; i++) reg[i] = row[i];
#pragma unroll
                for (int kx = 0; kx < 5; kx++) {
                    float wv = wc[ky * 5 + kx];
#pragma unroll
                    for (int x = 0; x < 21; x++) acc[x] = fmaf(reg[x + kx], wv, acc[x]);
                }
            }
        }
        float* outp = h2 + (size_t)n * H2_PER + r * 21;
#pragma unroll
        for (int x = 0; x < 21; x++) outp[x] = fmaxf(acc[x], 0.f);
    }
}

// ---------------------------------------------------------------------------
// K3: deconv2 (transposed 5x5, 60->24, full pad) + ELU
// out[co,y,x] = b[co] + sum_{ci,ky,kx} pad(h2)[ci][y+ky][x+kx] * w[ci][co][4-ky][4-kx]
// smem: padded input 60*29*29 = 50460 floats = 201840 B (weights via L2 LDG)
// ---------------------------------------------------------------------------
__global__ void deconv2_kernel(const float* __restrict__ h2,
                               const float* __restrict__ w,   // [60][24][5][5]
                               const float* __restrict__ b,   // [24]
                               float* __restrict__ h3) {
    extern __shared__ float sIn[];  // 60*29*29
    const int n = blockIdx.x;
    const int bd = blockDim.x;
    for (int i = threadIdx.x; i < 60 * 29 * 29; i += bd) sIn[i] = 0.f;
    __syncthreads();
    const float* in = h2 + (size_t)n * H2_PER;
    for (int i = threadIdx.x; i < H2_PER; i += bd) {
        int ci = i / 441, rem = i % 441;
        int y = rem / 21, x = rem % 21;
        sIn[ci * 841 + (y + 4) * 29 + (x + 4)] = in[i];
    }
    __syncthreads();

    // 600 rows: r = co*25 + y, each 25 outputs
    for (int r = threadIdx.x; r < 600; r += bd) {
        int co = r / 25, y = r % 25;
        float acc[25];
        float bias = b[co];
#pragma unroll
        for (int x = 0; x < 25; x++) acc[x] = bias;
        for (int ci = 0; ci < 60; ci++) {
            const float* inc = sIn + ci * 841 + y * 29;
            const float* wc = w + ci * 600 + co * 25;
#pragma unroll
            for (int ky = 0; ky < 5; ky++) {
                float reg[29];
                const float* row = inc + ky * 29;
#pragma unroll
                for (int i = 0; i < 29; i++) reg[i] = row[i];
#pragma unroll
                for (int kx = 0; kx < 5; kx++) {
                    float wv = __ldg(&wc[(4 - ky) * 5 + (4 - kx)]);
#pragma unroll
                    for (int x = 0; x < 25; x++) acc[x] = fmaf(reg[x + kx], wv, acc[x]);
                }
            }
        }
        float* outp = h3 + (size_t)n * H3_PER + r * 25;
#pragma unroll
        for (int x = 0; x < 25; x++) outp[x] = elu1(acc[x]);
    }
}

// ---------------------------------------------------------------------------
// K4: deconv1 (transposed 2x8x8, 24->1) fused with per-patch einsum+bias -> p
// p[n,y,x] = cst + sum_{ci,ky,kx} pad(h3)[ci][y+ky][x+kx] * Wf[ci][ky][kx]
//   Wf[ci][ky][kx] = lw0*w1[ci][0][0][7-ky][7-kx] + lw1*w1[ci][0][1][7-ky][7-kx]
//   cst = (lw0+lw1)*b1 + lin_b[n]
// smem: 24*39*39 = 36504 + Wf 1536 floats = 152160 B
// ---------------------------------------------------------------------------
__global__ void deconv1_p_kernel(const float* __restrict__ h3,
                                 const float* __restrict__ w1,    // [24][1][2][8][8]
                                 const float* __restrict__ b1,    // [1]
                                 const float* __restrict__ lin_w, // [N][2]
                                 const float* __restrict__ lin_b, // [N]
                                 float* __restrict__ P) {
    extern __shared__ float sm[];
    float* sIn = sm;          // 36504
    float* sWf = sm + 36504;  // 1536
    const int n = blockIdx.x;
    const int bd = blockDim.x;
    const float lw0 = lin_w[2 * n], lw1 = lin_w[2 * n + 1];

    for (int i = threadIdx.x; i < 24 * 39 * 39; i += bd) sIn[i] = 0.f;
    __syncthreads();
    const float* in = h3 + (size_t)n * H3_PER;
    for (int i = threadIdx.x; i < H3_PER; i += bd) {
        int ci = i / 625, rem = i % 625;
        int y = rem / 25, x = rem % 25;
        sIn[ci * 1521 + (y + 7) * 39 + (x + 7)] = in[i];
    }
    for (int i = threadIdx.x; i < 1536; i += bd) {
        int ci = i / 64, rem = i % 64;
        int ky = rem / 8, kx = rem % 8;
        int fidx = ci * 128 + (7 - ky) * 8 + (7 - kx);
        sWf[i] = lw0 * w1[fidx] + lw1 * w1[fidx + 64];
    }
    __syncthreads();

    const float cst = (lw0 + lw1) * b1[0] + lin_b[n];
    // 256 threads, each computes 4 consecutive x outputs
    const int t = threadIdx.x;
    const int y = t >> 3;
    const int x0 = (t & 7) * 4;
    float acc[4] = {cst, cst, cst, cst};
    for (int ci = 0; ci < 24; ci++) {
        const float* base = sIn + ci * 1521 + y * 39 + x0;
        const float* wb = sWf + ci * 64;
#pragma unroll
        for (int ky = 0; ky < 8; ky++) {
            float reg[11];
            const float* row = base + ky * 39;
#pragma unroll
            for (int i = 0; i < 11; i++) reg[i] = row[i];
            const float* wr = wb + ky * 8;
#pragma unroll
            for (int kx = 0; kx < 8; kx++) {
                float wv = wr[kx];
#pragma unroll
                for (int j = 0; j < 4; j++) acc[j] = fmaf(reg[j + kx], wv, acc[j]);
            }
        }
    }
    float* outp = P + (size_t)n * 1024 + y * 32 + x0;
#pragma unroll
    for (int j = 0; j < 4; j++) outp[j] = acc[j];
}

// ---------------------------------------------------------------------------
// K5: overlap-add scatter + final residual
// out[Y,X] = x2[Y,X] - linear1_w * sum_{contributing patches} p[n][Y-16i][X-16j]
// ---------------------------------------------------------------------------
__global__ void final_kernel(const float* __restrict__ x2,
                             const float* __restrict__ P,
                             const float* __restrict__ linear1_w,
                             float* __restrict__ out) {
    int idx = blockIdx.x * blockDim.x + threadIdx.x;
    if (idx >= HH * WW) return;
    int Y = idx >> 10, X = idx & 1023;
    float s = 0.f;
    int iy = Y >> 4, ix = X >> 4;
#pragma unroll
    for (int di = 0; di < 2; di++) {
        int i = iy - di;
        if (i < 0 || i > 62) continue;
        int py = Y - i * 16;
        if (py >= 32) continue;
#pragma unroll
        for (int dj = 0; dj < 2; dj++) {
            int j = ix - dj;
            if (j < 0 || j > 62) continue;
            int px = X - j * 16;
            if (px >= 32) continue;
            s += P[(size_t)(i * NHH + j) * 1024 + py * 32 + px];
        }
    }
    out[idx] = x2[idx] - s * linear1_w[0];
}

// ---------------------------------------------------------------------------
extern "C" void kernel_launch(void* const* d_in, const int* in_sizes, int n_in,
                              void* d_out, int out_size) {
    const float* x1        = (const float*)d_in[0];
    const float* x2        = (const float*)d_in[1];
    const float* conv1_w   = (const float*)d_in[2];
    const float* conv1_b   = (const float*)d_in[3];
    const float* conv2_w   = (const float*)d_in[4];
    const float* conv2_b   = (const float*)d_in[5];
    const float* deconv2_w = (const float*)d_in[6];
    const float* deconv2_b = (const float*)d_in[7];
    const float* deconv1_w = (const float*)d_in[8];
    const float* deconv1_b = (const float*)d_in[9];
    const float* lin_w     = (const float*)d_in[10];
    const float* lin_b     = (const float*)d_in[11];
    const float* linear1_w = (const float*)d_in[12];
    float* out = (float*)d_out;

    float *h1, *h2, *h3, *P;
    cudaGetSymbolAddress((void**)&h1, g_h1);
    cudaGetSymbolAddress((void**)&h2, g_h2);
    cudaGetSymbolAddress((void**)&h3, g_h3);
    cudaGetSymbolAddress((void**)&P,  g_p);

    const int smem2 = (15000 + 36000) * 4;   // 204000
    const int smem3 = (60 * 29 * 29) * 4;    // 201840
    const int smem4 = (36504 + 1536) * 4;    // 152160
    cudaFuncSetAttribute(conv2_kernel,    cudaFuncAttributeMaxDynamicSharedMemorySize, smem2);
    cudaFuncSetAttribute(deconv2_kernel,  cudaFuncAttributeMaxDynamicSharedMemorySize, smem3);
    cudaFuncSetAttribute(deconv1_p_kernel,cudaFuncAttributeMaxDynamicSharedMemorySize, smem4);

    conv1_kernel<<<NP, 256>>>(x1, x2, conv1_w, conv1_b, h1);
    conv2_kernel<<<NP, 512, smem2>>>(h1, conv2_w, conv2_b, h2);
    deconv2_kernel<<<NP, 256, smem3>>>(h2, deconv2_w, deconv2_b, h3);
    deconv1_p_kernel<<<NP, 256, smem4>>>(h3, deconv1_w, deconv1_b, lin_w, lin_b, P);
    final_kernel<<<(HH * WW + 255) / 256, 256>>>(x2, P, linear1_w, out);
}